// round 9
// baseline (speedup 1.0000x reference)
#include <cuda_runtime.h>
#include <cuda_bf16.h>
#include <math.h>
#include <cstdint>

#define EPSV 1e-5f

// ---------------- scratch (device globals; allocation-free) ----------------
__device__ __nv_bfloat16 g_qb[16 * 4096 * 64];   // q: [bh][n][c], pre-scaled 0.125*log2e
__device__ uint4 g_kf4[16 * 512 * 2 * 32];       // K frags: [bh][kt][sp][lane]
__device__ uint4 g_vf4[16 * 32 * 8 * 4 * 32];    // V frags: [bh][chunk][ct][sp][lane]
__device__ float g_ao[4 * 256 * 4096];           // attention out [b][c][n] fp32
__device__ float g_part[32 * 16 * 2];
__device__ float g_mean[32];
__device__ float g_rstd[32];

// ======================= helpers =======================
__device__ __forceinline__ uint32_t f2tf(float f) {
    uint32_t r;
    asm("cvt.rna.tf32.f32 %0, %1;" : "=r"(r) : "f"(f));
    return r;
}
__device__ __forceinline__ uint32_t pbf2(float lo, float hi) {
    __nv_bfloat162 t = __floats2bfloat162_rn(lo, hi);
    return *(uint32_t*)&t;
}
__device__ __forceinline__ float ex2(float x) {
    float r;
    asm("ex2.approx.ftz.f32 %0, %1;" : "=f"(r) : "f"(x));
    return r;
}
__device__ __forceinline__ void mma_tf32(float d[4], const uint4 a, const uint2 b) {
    asm volatile("mma.sync.aligned.m16n8k8.row.col.f32.tf32.tf32.f32 "
                 "{%0,%1,%2,%3}, {%4,%5,%6,%7}, {%8,%9}, {%0,%1,%2,%3};"
                 : "+f"(d[0]), "+f"(d[1]), "+f"(d[2]), "+f"(d[3])
                 : "r"(a.x), "r"(a.y), "r"(a.z), "r"(a.w), "r"(b.x), "r"(b.y));
}
__device__ __forceinline__ void mma_bf16(float d[4], const uint32_t a0, const uint32_t a1,
                                         const uint32_t a2, const uint32_t a3,
                                         const uint32_t b0, const uint32_t b1) {
    asm volatile("mma.sync.aligned.m16n8k16.row.col.f32.bf16.bf16.f32 "
                 "{%0,%1,%2,%3}, {%4,%5,%6,%7}, {%8,%9}, {%0,%1,%2,%3};"
                 : "+f"(d[0]), "+f"(d[1]), "+f"(d[2]), "+f"(d[3])
                 : "r"(a0), "r"(a1), "r"(a2), "r"(a3), "r"(b0), "r"(b1));
}
__device__ __forceinline__ void cp16(uint32_t saddr, const void* gaddr) {
    asm volatile("cp.async.cg.shared.global [%0], [%1], 16;" :: "r"(saddr), "l"(gaddr));
}
#define CP_COMMIT() asm volatile("cp.async.commit_group;" ::: "memory")
#define CP_WAIT1()  asm volatile("cp.async.wait_group 1;" ::: "memory")

// ---------------- GroupNorm stats ----------------
__global__ void gn_partial(const float* __restrict__ x) {
    int bg = blockIdx.x;
    int chunk = blockIdx.y;
    const float4* p = (const float4*)(x + (size_t)bg * 32 * 4096 + (size_t)chunk * 8192);
    float s = 0.f, q = 0.f;
#pragma unroll
    for (int i = 0; i < 8; i++) {
        float4 v = p[threadIdx.x + i * 256];
        s += v.x + v.y + v.z + v.w;
        q += v.x * v.x + v.y * v.y + v.z * v.z + v.w * v.w;
    }
    __shared__ float ss[256], sq[256];
    ss[threadIdx.x] = s; sq[threadIdx.x] = q;
    __syncthreads();
    for (int o = 128; o > 0; o >>= 1) {
        if (threadIdx.x < o) {
            ss[threadIdx.x] += ss[threadIdx.x + o];
            sq[threadIdx.x] += sq[threadIdx.x + o];
        }
        __syncthreads();
    }
    if (threadIdx.x == 0) {
        g_part[(bg * 16 + chunk) * 2 + 0] = ss[0];
        g_part[(bg * 16 + chunk) * 2 + 1] = sq[0];
    }
}

__global__ void gn_finalize() {
    int t = threadIdx.x;
    float s = 0.f, q = 0.f;
#pragma unroll
    for (int i = 0; i < 16; i++) {
        s += g_part[(t * 16 + i) * 2 + 0];
        q += g_part[(t * 16 + i) * 2 + 1];
    }
    const float inv = 1.0f / 131072.0f;
    float mean = s * inv;
    float var = q * inv - mean * mean;
    g_mean[t] = mean;
    g_rstd[t] = rsqrtf(var + EPSV);
}

// ---------------- QKV GEMM (tf32 mma, GN fused, 2 M-tiles per block) ----------------
// grid (32 nb, 3 qkvi, 4 b), 256 thr. Each block computes a 256x128 C-tile
// (q, k, or v), sharing ONE B-fragment load across 2 M-tiles (halves x L2 traffic).
#define QKV_SMEM 35584

__global__ void __launch_bounds__(256) gemm_qkv(const float* __restrict__ W,
                                                const float* __restrict__ x,
                                                const float* __restrict__ bias,
                                                const float* __restrict__ nw,
                                                const float* __restrict__ nbv) {
    extern __shared__ char sm[];
    uint4* Af = (uint4*)sm;                         // 32 frags * 32 lanes (16 KB)
    uint2* Bf = (uint2*)(sm + 16384);               // 32 frags * 32 lanes (8 KB)
    unsigned short* Ost = (unsigned short*)sm;      // [128][130] bf16 overlay
    float* sc = (float*)(sm + 33536);
    float* sh = (float*)(sm + 34560);

    const int tid = threadIdx.x, wid = tid >> 5, lane = tid & 31;
    const int gr = lane >> 2, tg = lane & 3;
    const int n0 = blockIdx.x * 128, qkvi = blockIdx.y, b = blockIdx.z;
    const int wm = wid & 3, wn = wid >> 2;

    {
        int c = tid;
        int bg = b * 8 + (c >> 5);
        float s = g_rstd[bg] * nw[c];
        sc[c] = s;
        sh[c] = nbv[c] - g_mean[bg] * s;
    }
    __syncthreads();

    float acc[2][2][8][4] = {};
    const float* Abase = W + (size_t)(qkvi * 256) * 256;

    for (int k0 = 0; k0 < 256; k0 += 16) {
#pragma unroll
        for (int i = 0; i < 4; i++) {
            int f = wid * 4 + i;
            int m = f >> 4, t = (f >> 1) & 7, s = f & 1;
            const float* ap = Abase + (size_t)(m * 128 + t * 16 + gr) * 256 + k0 + s * 8 + tg;
            uint4 u;
            u.x = f2tf(ap[0]); u.y = f2tf(ap[2048]);
            u.z = f2tf(ap[4]); u.w = f2tf(ap[2052]);
            Af[f * 32 + lane] = u;
        }
#pragma unroll
        for (int i = 0; i < 4; i++) {
            int f = wid * 4 + i;
            int u_ = f >> 1, s = f & 1;
            int c = k0 + s * 8 + tg;
            int n = n0 + u_ * 8 + gr;
            const float* xp = x + ((size_t)(b * 256 + c)) * 4096 + n;
            float h0 = xp[0] * sc[c] + sh[c];
            float h1 = xp[4 * 4096] * sc[c + 4] + sh[c + 4];
            uint2 u;
            u.x = f2tf(h0); u.y = f2tf(h1);
            Bf[f * 32 + lane] = u;
        }
        __syncthreads();
#pragma unroll
        for (int s = 0; s < 2; s++) {
            uint4 a00 = Af[(0 * 16 + (wm * 2 + 0) * 2 + s) * 32 + lane];
            uint4 a01 = Af[(0 * 16 + (wm * 2 + 1) * 2 + s) * 32 + lane];
            uint4 a10 = Af[(1 * 16 + (wm * 2 + 0) * 2 + s) * 32 + lane];
            uint4 a11 = Af[(1 * 16 + (wm * 2 + 1) * 2 + s) * 32 + lane];
#pragma unroll
            for (int u_ = 0; u_ < 8; u_++) {
                uint2 bb = Bf[((wn * 8 + u_) * 2 + s) * 32 + lane];
                mma_tf32(acc[0][0][u_], a00, bb);
                mma_tf32(acc[0][1][u_], a01, bb);
                mma_tf32(acc[1][0][u_], a10, bb);
                mma_tf32(acc[1][1][u_], a11, bb);
            }
        }
        __syncthreads();
    }

    // epilogue: two 128-row sub-tiles, mb = qkvi*2 + m
#pragma unroll
    for (int m = 0; m < 2; m++) {
        int mb = qkvi * 2 + m;
        const float scale = (mb < 2) ? 0.125f * 1.4426950408889634f : 1.0f;
#pragma unroll
        for (int t = 0; t < 2; t++) {
            int o_l = wm * 32 + t * 16 + gr;
            float bi0 = bias[mb * 128 + o_l];
            float bi1 = bias[mb * 128 + o_l + 8];
#pragma unroll
            for (int u_ = 0; u_ < 8; u_++) {
                int n_l = wn * 64 + u_ * 8 + 2 * tg;
                uint32_t w0 = pbf2((acc[m][t][u_][0] + bi0) * scale, (acc[m][t][u_][1] + bi0) * scale);
                uint32_t w1 = pbf2((acc[m][t][u_][2] + bi1) * scale, (acc[m][t][u_][3] + bi1) * scale);
                *(uint32_t*)&Ost[o_l * 130 + n_l] = w0;
                *(uint32_t*)&Ost[(o_l + 8) * 130 + n_l] = w1;
            }
        }
        __syncthreads();

        if (mb < 2) {
#pragma unroll
            for (int p = 0; p < 32; p++) {
                int idx = tid + p * 256;
                int n = idx >> 6;
                int ho = (idx >> 5) & 1;
                int cw = idx & 31;
                unsigned short lo = Ost[(ho * 64 + 2 * cw) * 130 + n];
                unsigned short hi = Ost[(ho * 64 + 2 * cw + 1) * 130 + n];
                uint32_t val = (uint32_t)lo | ((uint32_t)hi << 16);
                int bh = b * 4 + mb * 2 + ho;
                ((uint32_t*)g_qb)[((size_t)bh * 4096 + n0 + n) * 32 + cw] = val;
            }
        } else if (mb < 4) {
#pragma unroll
            for (int p = 0; p < 8; p++) {
                int e = tid + p * 256;
                int ln = e & 31, sp = (e >> 5) & 1, kt = (e >> 6) & 15, ho = e >> 10;
                int egr = ln >> 2, etg = ln & 3;
                int n = kt * 8 + egr;
                uint4 r;
                {
                    int c0 = ho * 64 + (2 * sp) * 16 + 2 * etg;
                    r.x = (uint32_t)Ost[c0 * 130 + n] | ((uint32_t)Ost[(c0 + 1) * 130 + n] << 16);
                    r.y = (uint32_t)Ost[(c0 + 8) * 130 + n] | ((uint32_t)Ost[(c0 + 9) * 130 + n] << 16);
                }
                {
                    int c0 = ho * 64 + (2 * sp + 1) * 16 + 2 * etg;
                    r.z = (uint32_t)Ost[c0 * 130 + n] | ((uint32_t)Ost[(c0 + 1) * 130 + n] << 16);
                    r.w = (uint32_t)Ost[(c0 + 8) * 130 + n] | ((uint32_t)Ost[(c0 + 9) * 130 + n] << 16);
                }
                int bh = b * 4 + (mb & 1) * 2 + ho;
                g_kf4[(((size_t)bh * 512 + (n0 >> 3) + kt) * 2 + sp) * 32 + ln] = r;
            }
        } else {
            int chv = blockIdx.x;
#pragma unroll
            for (int p = 0; p < 8; p++) {
                int e = tid + p * 256;
                int ln = e & 31, sp = (e >> 5) & 3, ct = (e >> 7) & 7, ho = e >> 10;
                int egr = ln >> 2, etg = ln & 3;
                int c = ho * 64 + ct * 8 + egr;
                uint4 r;
                {
                    int nn = (2 * sp) * 16 + 2 * etg;
                    r.x = *(uint32_t*)&Ost[c * 130 + nn];
                    r.y = *(uint32_t*)&Ost[c * 130 + nn + 8];
                }
                {
                    int nn = (2 * sp + 1) * 16 + 2 * etg;
                    r.z = *(uint32_t*)&Ost[c * 130 + nn];
                    r.w = *(uint32_t*)&Ost[c * 130 + nn + 8];
                }
                int bh = b * 4 + (mb - 4) * 2 + ho;
                g_vf4[((((size_t)bh * 32 + chv) * 8 + ct) * 4 + sp) * 32 + ln] = r;
            }
        }
        __syncthreads();
    }
}

// ---------------- Proj GEMM (tf32 mma) + bias + residual ----------------
__global__ void __launch_bounds__(256) gemm_proj(const float* __restrict__ W,
                                                 const float* __restrict__ bias,
                                                 const float* __restrict__ resid,
                                                 float* __restrict__ outp) {
    __shared__ uint4 Af[16 * 32];
    __shared__ uint2 Bf[32 * 32];
    const int tid = threadIdx.x, wid = tid >> 5, lane = tid & 31;
    const int gr = lane >> 2, tg = lane & 3;
    const int n0 = blockIdx.x * 128, mb = blockIdx.y, b = blockIdx.z;
    const int wm = wid & 3, wn = wid >> 2;

    float acc[2][8][4] = {};
    const float* Abase = W + (size_t)(mb * 128) * 256;

    for (int k0 = 0; k0 < 256; k0 += 16) {
#pragma unroll
        for (int i = 0; i < 2; i++) {
            int f = wid * 2 + i;
            int t = f >> 1, s = f & 1;
            const float* ap = Abase + (size_t)(t * 16 + gr) * 256 + k0 + s * 8 + tg;
            uint4 u;
            u.x = f2tf(ap[0]); u.y = f2tf(ap[2048]);
            u.z = f2tf(ap[4]); u.w = f2tf(ap[2052]);
            Af[f * 32 + lane] = u;
        }
#pragma unroll
        for (int i = 0; i < 4; i++) {
            int f = wid * 4 + i;
            int u_ = f >> 1, s = f & 1;
            int c = k0 + s * 8 + tg;
            int n = n0 + u_ * 8 + gr;
            const float* xp = g_ao + ((size_t)(b * 256 + c)) * 4096 + n;
            uint2 u;
            u.x = f2tf(xp[0]);
            u.y = f2tf(xp[4 * 4096]);
            Bf[f * 32 + lane] = u;
        }
        __syncthreads();
#pragma unroll
        for (int s = 0; s < 2; s++) {
            uint4 a0 = Af[((wm * 2 + 0) * 2 + s) * 32 + lane];
            uint4 a1 = Af[((wm * 2 + 1) * 2 + s) * 32 + lane];
#pragma unroll
            for (int u_ = 0; u_ < 8; u_++) {
                uint2 bb = Bf[((wn * 8 + u_) * 2 + s) * 32 + lane];
                mma_tf32(acc[0][u_], a0, bb);
                mma_tf32(acc[1][u_], a1, bb);
            }
        }
        __syncthreads();
    }

#pragma unroll
    for (int t = 0; t < 2; t++) {
        int o = mb * 128 + wm * 32 + t * 16 + gr;
        float bi0 = bias[o], bi1 = bias[o + 8];
#pragma unroll
        for (int u_ = 0; u_ < 8; u_++) {
            size_t off = ((size_t)(b * 256 + o)) * 4096 + n0 + wn * 64 + u_ * 8 + 2 * tg;
            float2 r0 = *(const float2*)(resid + off);
            float2 o0;
            o0.x = acc[t][u_][0] + bi0 + r0.x;
            o0.y = acc[t][u_][1] + bi0 + r0.y;
            *(float2*)(outp + off) = o0;
            size_t off8 = off + 8 * 4096;
            float2 r1 = *(const float2*)(resid + off8);
            float2 o1;
            o1.x = acc[t][u_][2] + bi1 + r1.x;
            o1.y = acc[t][u_][3] + bi1 + r1.y;
            *(float2*)(outp + off8) = o1;
        }
    }
}

// ---------------- bf16 mma flash attention: phase-staggered key groups ----------
// grid (32 q-tiles, 16 bh), 128 thr = 4 warps x 32 q rows (2 m16 A-tiles each).
// smem: 3 stages x (K 16KB | V 16KB) = 96KB.
// Key-group order rotated per block by (bid.x+bid.y)&3 to break phase-locking
// between the two co-resident CTAs sharing each SMSP's tensor/MUFU pipes.
#define ATT_SMEM 98304

__global__ void __launch_bounds__(128, 2) attn_mma() {
    extern __shared__ char smc[];
    uint32_t sbase;
    asm("{ .reg .u64 t; cvta.to.shared.u64 t, %1; cvt.u32.u64 %0, t; }" : "=r"(sbase) : "l"(smc));

    const int tid = threadIdx.x, wid = tid >> 5, lane = tid & 31;
    const int gr = lane >> 2, tg = lane & 3;
    const int qt = blockIdx.x, bh = blockIdx.y;
    const int b = bh >> 2, hh = bh & 3;
    const int w32 = wid * 32;
    const int rot = (blockIdx.x + blockIdx.y) & 3;
    const int G0 = rot, G1 = (rot + 1) & 3, G2 = (rot + 2) & 3, G3 = (rot + 3) & 3;

    const __nv_bfloat16* qg = g_qb + ((size_t)bh * 4096 + qt * 128) * 64;
    const uint4* kfg = g_kf4 + (size_t)bh * 32768;
    const uint4* vfg = g_vf4 + (size_t)bh * 32768;

    // Q fragments: 2 A-row-tiles (32 q rows) x 4 ksteps of 16 over c=64
    uint32_t qa[2][4][4];
#pragma unroll
    for (int at = 0; at < 2; at++) {
#pragma unroll
        for (int s = 0; s < 4; s++) {
            const __nv_bfloat16* base = qg + (size_t)(w32 + at * 16 + gr) * 64 + s * 16 + 2 * tg;
            qa[at][s][0] = *(const uint32_t*)(base);
            qa[at][s][1] = *(const uint32_t*)(base + 8 * 64);
            qa[at][s][2] = *(const uint32_t*)(base + 8);
            qa[at][s][3] = *(const uint32_t*)(base + 8 * 64 + 8);
        }
    }

    float oacc[2][8][4] = {};
    float rs[2][2] = {};

#define PREFETCH(ch) do {                                                     \
        int _c = (ch);                                                       \
        if (_c < 32) {                                                       \
            uint32_t _sk = sbase + (uint32_t)(_c % 3) * 32768;               \
            const uint4* _gk = kfg + (size_t)_c * 1024;                      \
            const uint4* _gv = vfg + (size_t)_c * 1024;                      \
            _Pragma("unroll")                                                \
            for (int _i = 0; _i < 8; _i++)                                   \
                cp16(_sk + (tid + _i * 128) * 16, _gk + tid + _i * 128);     \
            _Pragma("unroll")                                                \
            for (int _i = 0; _i < 8; _i++)                                   \
                cp16(_sk + 16384 + (tid + _i * 128) * 16, _gv + tid + _i * 128); \
        }                                                                    \
        CP_COMMIT();                                                         \
    } while (0)

#define S_CALC(dst, g) do {                                                  \
        _Pragma("unroll")                                                    \
        for (int _u = 0; _u < 4; _u++) {                                     \
            uint4 _k0 = Kf4[(((g) * 4 + _u) * 2 + 0) * 32 + lane];           \
            uint4 _k1 = Kf4[(((g) * 4 + _u) * 2 + 1) * 32 + lane];           \
            _Pragma("unroll")                                                \
            for (int _at = 0; _at < 2; _at++) {                              \
                dst[_at][_u][0] = 0.f; dst[_at][_u][1] = 0.f;                \
                dst[_at][_u][2] = 0.f; dst[_at][_u][3] = 0.f;                \
                mma_bf16(dst[_at][_u], qa[_at][0][0], qa[_at][0][1], qa[_at][0][2], qa[_at][0][3], _k0.x, _k0.y); \
                mma_bf16(dst[_at][_u], qa[_at][1][0], qa[_at][1][1], qa[_at][1][2], qa[_at][1][3], _k0.z, _k0.w); \
                mma_bf16(dst[_at][_u], qa[_at][2][0], qa[_at][2][1], qa[_at][2][2], qa[_at][2][3], _k1.x, _k1.y); \
                mma_bf16(dst[_at][_u], qa[_at][3][0], qa[_at][3][1], qa[_at][3][2], qa[_at][3][3], _k1.z, _k1.w); \
            }                                                                \
        }                                                                    \
    } while (0)

#define E_CALC(pdst, src) do {                                               \
        _Pragma("unroll")                                                    \
        for (int _at = 0; _at < 2; _at++) {                                  \
            _Pragma("unroll")                                                \
            for (int _u = 0; _u < 4; _u++) {                                 \
                float _e0 = ex2(src[_at][_u][0]);                            \
                float _e1 = ex2(src[_at][_u][1]);                            \
                float _e2 = ex2(src[_at][_u][2]);                            \
                float _e3 = ex2(src[_at][_u][3]);                            \
                rs[_at][0] += _e0 + _e1;                                     \
                rs[_at][1] += _e2 + _e3;                                     \
                pdst[_at][_u][0] = pbf2(_e0, _e1);                           \
                pdst[_at][_u][1] = pbf2(_e2, _e3);                           \
            }                                                                \
        }                                                                    \
    } while (0)

#define V_CALC(g, psrc) do {                                                 \
        _Pragma("unroll")                                                    \
        for (int _ct = 0; _ct < 8; _ct++) {                                  \
            uint4 _v = Vf4[(_ct * 4 + (g)) * 32 + lane];                     \
            _Pragma("unroll")                                                \
            for (int _at = 0; _at < 2; _at++) {                              \
                mma_bf16(oacc[_at][_ct], psrc[_at][0][0], psrc[_at][0][1],   \
                         psrc[_at][1][0], psrc[_at][1][1], _v.x, _v.y);      \
                mma_bf16(oacc[_at][_ct], psrc[_at][2][0], psrc[_at][2][1],   \
                         psrc[_at][3][0], psrc[_at][3][1], _v.z, _v.w);      \
            }                                                                \
        }                                                                    \
    } while (0)

    PREFETCH(0);
    PREFETCH(1);

    for (int ch = 0; ch < 32; ch++) {
        CP_WAIT1();
        __syncthreads();
        PREFETCH(ch + 2);

        const uint4* Kf4 = (const uint4*)(smc + (ch % 3) * 32768);
        const uint4* Vf4 = (const uint4*)(smc + (ch % 3) * 32768 + 16384);

        float sA[2][4][4], sB[2][4][4];
        uint32_t pA[2][4][2], pB[2][4][2];

        S_CALC(sA, G0);
        E_CALC(pA, sA);
        S_CALC(sB, G1);
        V_CALC(G0, pA);
        E_CALC(pB, sB);
        S_CALC(sA, G2);
        V_CALC(G1, pB);
        E_CALC(pA, sA);
        S_CALC(sB, G3);
        V_CALC(G2, pA);
        E_CALC(pB, sB);
        V_CALC(G3, pB);
    }
#undef PREFETCH
#undef S_CALC
#undef E_CALC
#undef V_CALC

    // full row sums (quad lanes share rows)
    float ri[2][2];
#pragma unroll
    for (int at = 0; at < 2; at++) {
#pragma unroll
        for (int r = 0; r < 2; r++) {
            float v = rs[at][r];
            v += __shfl_xor_sync(0xffffffffu, v, 1);
            v += __shfl_xor_sync(0xffffffffu, v, 2);
            ri[at][r] = 1.0f / v;
        }
    }

    // stage O [64 c][132 pitch] fp32, then coalesced write
    float* Os = (float*)smc;
    __syncthreads();
#pragma unroll
    for (int at = 0; at < 2; at++) {
#pragma unroll
        for (int ct = 0; ct < 8; ct++) {
            int c = ct * 8 + 2 * tg;
            int q0 = w32 + at * 16 + gr;
            Os[(size_t)c * 132 + q0] = oacc[at][ct][0] * ri[at][0];
            Os[(size_t)(c + 1) * 132 + q0] = oacc[at][ct][1] * ri[at][0];
            Os[(size_t)c * 132 + q0 + 8] = oacc[at][ct][2] * ri[at][1];
            Os[(size_t)(c + 1) * 132 + q0 + 8] = oacc[at][ct][3] * ri[at][1];
        }
    }
    __syncthreads();

    float* dst = g_ao + ((size_t)(b * 256 + hh * 64)) * 4096 + qt * 128;
#pragma unroll
    for (int p = 0; p < 16; p++) {
        int idx = tid + p * 128;
        int c = idx >> 5, q4 = idx & 31;
        float4 v = *(const float4*)(Os + (size_t)c * 132 + q4 * 4);
        *(float4*)(dst + (size_t)c * 4096 + q4 * 4) = v;
    }
}

// ---------------- launch ----------------
extern "C" void kernel_launch(void* const* d_in, const int* in_sizes, int n_in,
                              void* d_out, int out_size) {
    (void)in_sizes; (void)n_in; (void)out_size;
    const float* x      = (const float*)d_in[0];
    const float* norm_w = (const float*)d_in[1];
    const float* norm_b = (const float*)d_in[2];
    const float* qkv_w  = (const float*)d_in[3];
    const float* qkv_b  = (const float*)d_in[4];
    const float* proj_w = (const float*)d_in[5];
    const float* proj_b = (const float*)d_in[6];
    float* out = (float*)d_out;

    cudaFuncSetAttribute(attn_mma, cudaFuncAttributeMaxDynamicSharedMemorySize, ATT_SMEM);

    gn_partial<<<dim3(32, 16), 256>>>(x);
    gn_finalize<<<1, 32>>>();

    gemm_qkv<<<dim3(32, 3, 4), 256, QKV_SMEM>>>(qkv_w, x, qkv_b, norm_w, norm_b);

    attn_mma<<<dim3(32, 16), 128, ATT_SMEM>>>();

    gemm_proj<<<dim3(32, 2, 4), 256>>>(proj_w, proj_b, x, out);
}

// round 10
// speedup vs baseline: 1.1808x; 1.1808x over previous
#include <cuda_runtime.h>
#include <cuda_bf16.h>
#include <math.h>
#include <cstdint>

#define EPSV 1e-5f

// ---------------- scratch (device globals; allocation-free) ----------------
__device__ __nv_bfloat16 g_qb[16 * 4096 * 64];   // q: [bh][n][c], pre-scaled 0.125*log2e
__device__ uint4 g_kf4[16 * 512 * 2 * 32];       // K frags: [bh][kt][sp][lane]
__device__ uint4 g_vf4[16 * 32 * 8 * 4 * 32];    // V frags: [bh][chunk][ct][sp][lane]
__device__ float g_ao[4 * 256 * 4096];           // attention out [b][c][n] fp32
__device__ float g_part[32 * 16 * 2];
__device__ float g_mean[32];
__device__ float g_rstd[32];

// ======================= helpers =======================
__device__ __forceinline__ uint32_t pbf2(float lo, float hi) {
    __nv_bfloat162 t = __floats2bfloat162_rn(lo, hi);
    return *(uint32_t*)&t;
}
__device__ __forceinline__ float ex2(float x) {
    float r;
    asm("ex2.approx.ftz.f32 %0, %1;" : "=f"(r) : "f"(x));
    return r;
}
__device__ __forceinline__ void mma_bf16(float d[4], const uint32_t a0, const uint32_t a1,
                                         const uint32_t a2, const uint32_t a3,
                                         const uint32_t b0, const uint32_t b1) {
    asm volatile("mma.sync.aligned.m16n8k16.row.col.f32.bf16.bf16.f32 "
                 "{%0,%1,%2,%3}, {%4,%5,%6,%7}, {%8,%9}, {%0,%1,%2,%3};"
                 : "+f"(d[0]), "+f"(d[1]), "+f"(d[2]), "+f"(d[3])
                 : "r"(a0), "r"(a1), "r"(a2), "r"(a3), "r"(b0), "r"(b1));
}
__device__ __forceinline__ void cp16(uint32_t saddr, const void* gaddr) {
    asm volatile("cp.async.cg.shared.global [%0], [%1], 16;" :: "r"(saddr), "l"(gaddr));
}
#define CP_COMMIT() asm volatile("cp.async.commit_group;" ::: "memory")
#define CP_WAIT1()  asm volatile("cp.async.wait_group 1;" ::: "memory")

// ---------------- GroupNorm stats ----------------
__global__ void gn_partial(const float* __restrict__ x) {
    int bg = blockIdx.x;
    int chunk = blockIdx.y;
    const float4* p = (const float4*)(x + (size_t)bg * 32 * 4096 + (size_t)chunk * 8192);
    float s = 0.f, q = 0.f;
#pragma unroll
    for (int i = 0; i < 8; i++) {
        float4 v = p[threadIdx.x + i * 256];
        s += v.x + v.y + v.z + v.w;
        q += v.x * v.x + v.y * v.y + v.z * v.z + v.w * v.w;
    }
    __shared__ float ss[256], sq[256];
    ss[threadIdx.x] = s; sq[threadIdx.x] = q;
    __syncthreads();
    for (int o = 128; o > 0; o >>= 1) {
        if (threadIdx.x < o) {
            ss[threadIdx.x] += ss[threadIdx.x + o];
            sq[threadIdx.x] += sq[threadIdx.x + o];
        }
        __syncthreads();
    }
    if (threadIdx.x == 0) {
        g_part[(bg * 16 + chunk) * 2 + 0] = ss[0];
        g_part[(bg * 16 + chunk) * 2 + 1] = sq[0];
    }
}

__global__ void gn_finalize() {
    int t = threadIdx.x;
    float s = 0.f, q = 0.f;
#pragma unroll
    for (int i = 0; i < 16; i++) {
        s += g_part[(t * 16 + i) * 2 + 0];
        q += g_part[(t * 16 + i) * 2 + 1];
    }
    const float inv = 1.0f / 131072.0f;
    float mean = s * inv;
    float var = q * inv - mean * mean;
    g_mean[t] = mean;
    g_rstd[t] = rsqrtf(var + EPSV);
}

// ---------------- QKV GEMM (bf16 m16n8k16 mma, GN fused into B staging) -----------
// grid (32 nb, 6 mb, 4 b), 256 thr. mb: 0,1=q 2,3=k 4,5=v. C tile 128x128.
// smem: Af 4KB @0 | Bf 4KB @4096 | epilogue bf16 stage [128][130] overlay @0
//       sc @33280 | sh @34304 ; total 35328
#define QKV_SMEM 35328

__global__ void __launch_bounds__(256) gemm_qkv(const float* __restrict__ W,
                                                const float* __restrict__ x,
                                                const float* __restrict__ bias,
                                                const float* __restrict__ nw,
                                                const float* __restrict__ nbv) {
    extern __shared__ char sm[];
    uint4* Af = (uint4*)sm;                         // 8 frags * 32 lanes
    uint2* Bf = (uint2*)(sm + 4096);                // 16 frags * 32 lanes
    unsigned short* Ost = (unsigned short*)sm;      // [128][130] bf16 overlay
    float* sc = (float*)(sm + 33280);
    float* sh = (float*)(sm + 34304);

    const int tid = threadIdx.x, wid = tid >> 5, lane = tid & 31;
    const int gr = lane >> 2, tg = lane & 3;
    const int n0 = blockIdx.x * 128, mb = blockIdx.y, b = blockIdx.z;
    const int wm = wid & 3, wn = wid >> 2;

    {
        int c = tid;
        int bg = b * 8 + (c >> 5);
        float s = g_rstd[bg] * nw[c];
        sc[c] = s;
        sh[c] = nbv[c] - g_mean[bg] * s;
    }
    __syncthreads();

    float acc[2][8][4] = {};
    const float* Abase = W + (size_t)(mb * 128) * 256;

    for (int k0 = 0; k0 < 256; k0 += 16) {
        // A-frag for m-tile t=wid: rows t*16+gr(+8), k pairs 2tg(+1), +8
        {
            const float* ap = Abase + (size_t)(wid * 16 + gr) * 256 + k0 + 2 * tg;
            float2 w00 = *(const float2*)ap;
            float2 w10 = *(const float2*)(ap + 8 * 256);
            float2 w01 = *(const float2*)(ap + 8);
            float2 w11 = *(const float2*)(ap + 8 * 256 + 8);
            uint4 u;
            u.x = pbf2(w00.x, w00.y);
            u.y = pbf2(w10.x, w10.y);
            u.z = pbf2(w01.x, w01.y);
            u.w = pbf2(w11.x, w11.y);
            Af[wid * 32 + lane] = u;
        }
        // B-frags: 2 n-tiles per warp; h = GN(x) computed inline
#pragma unroll
        for (int i = 0; i < 2; i++) {
            int u_ = wid * 2 + i;
            int n = n0 + u_ * 8 + gr;
            int c0 = k0 + 2 * tg;
            const float* xp = x + ((size_t)(b * 256 + c0)) * 4096 + n;
            float h00 = xp[0] * sc[c0] + sh[c0];
            float h01 = xp[4096] * sc[c0 + 1] + sh[c0 + 1];
            float h10 = xp[8 * 4096] * sc[c0 + 8] + sh[c0 + 8];
            float h11 = xp[9 * 4096] * sc[c0 + 9] + sh[c0 + 9];
            uint2 v;
            v.x = pbf2(h00, h01);
            v.y = pbf2(h10, h11);
            Bf[u_ * 32 + lane] = v;
        }
        __syncthreads();
        uint4 a0 = Af[(wm * 2 + 0) * 32 + lane];
        uint4 a1 = Af[(wm * 2 + 1) * 32 + lane];
#pragma unroll
        for (int u_ = 0; u_ < 8; u_++) {
            uint2 bb = Bf[(wn * 8 + u_) * 32 + lane];
            mma_bf16(acc[0][u_], a0.x, a0.y, a0.z, a0.w, bb.x, bb.y);
            mma_bf16(acc[1][u_], a1.x, a1.y, a1.z, a1.w, bb.x, bb.y);
        }
        __syncthreads();
    }

    // stage bf16 [o_local][n_local] (q pre-scaled by 0.125*log2e)
    const float scale = (mb < 2) ? 0.125f * 1.4426950408889634f : 1.0f;
#pragma unroll
    for (int t = 0; t < 2; t++) {
        int o_l = wm * 32 + t * 16 + gr;
        float bi0 = bias[mb * 128 + o_l];
        float bi1 = bias[mb * 128 + o_l + 8];
#pragma unroll
        for (int u_ = 0; u_ < 8; u_++) {
            int n_l = wn * 64 + u_ * 8 + 2 * tg;
            uint32_t w0 = pbf2((acc[t][u_][0] + bi0) * scale, (acc[t][u_][1] + bi0) * scale);
            uint32_t w1 = pbf2((acc[t][u_][2] + bi1) * scale, (acc[t][u_][3] + bi1) * scale);
            *(uint32_t*)&Ost[o_l * 130 + n_l] = w0;
            *(uint32_t*)&Ost[(o_l + 8) * 130 + n_l] = w1;
        }
    }
    __syncthreads();

    if (mb < 2) {
#pragma unroll
        for (int p = 0; p < 32; p++) {
            int idx = tid + p * 256;
            int n = idx >> 6;
            int ho = (idx >> 5) & 1;
            int cw = idx & 31;
            unsigned short lo = Ost[(ho * 64 + 2 * cw) * 130 + n];
            unsigned short hi = Ost[(ho * 64 + 2 * cw + 1) * 130 + n];
            uint32_t val = (uint32_t)lo | ((uint32_t)hi << 16);
            int bh = b * 4 + mb * 2 + ho;
            ((uint32_t*)g_qb)[((size_t)bh * 4096 + n0 + n) * 32 + cw] = val;
        }
    } else if (mb < 4) {
#pragma unroll
        for (int p = 0; p < 8; p++) {
            int e = tid + p * 256;
            int ln = e & 31, sp = (e >> 5) & 1, kt = (e >> 6) & 15, ho = e >> 10;
            int egr = ln >> 2, etg = ln & 3;
            int n = kt * 8 + egr;
            uint4 r;
            {
                int c0 = ho * 64 + (2 * sp) * 16 + 2 * etg;
                r.x = (uint32_t)Ost[c0 * 130 + n] | ((uint32_t)Ost[(c0 + 1) * 130 + n] << 16);
                r.y = (uint32_t)Ost[(c0 + 8) * 130 + n] | ((uint32_t)Ost[(c0 + 9) * 130 + n] << 16);
            }
            {
                int c0 = ho * 64 + (2 * sp + 1) * 16 + 2 * etg;
                r.z = (uint32_t)Ost[c0 * 130 + n] | ((uint32_t)Ost[(c0 + 1) * 130 + n] << 16);
                r.w = (uint32_t)Ost[(c0 + 8) * 130 + n] | ((uint32_t)Ost[(c0 + 9) * 130 + n] << 16);
            }
            int bh = b * 4 + (mb & 1) * 2 + ho;
            g_kf4[(((size_t)bh * 512 + (n0 >> 3) + kt) * 2 + sp) * 32 + ln] = r;
        }
    } else {
        int chv = blockIdx.x;
#pragma unroll
        for (int p = 0; p < 8; p++) {
            int e = tid + p * 256;
            int ln = e & 31, sp = (e >> 5) & 3, ct = (e >> 7) & 7, ho = e >> 10;
            int egr = ln >> 2, etg = ln & 3;
            int c = ho * 64 + ct * 8 + egr;
            uint4 r;
            {
                int nn = (2 * sp) * 16 + 2 * etg;
                r.x = *(uint32_t*)&Ost[c * 130 + nn];
                r.y = *(uint32_t*)&Ost[c * 130 + nn + 8];
            }
            {
                int nn = (2 * sp + 1) * 16 + 2 * etg;
                r.z = *(uint32_t*)&Ost[c * 130 + nn];
                r.w = *(uint32_t*)&Ost[c * 130 + nn + 8];
            }
            int bh = b * 4 + (mb - 4) * 2 + ho;
            g_vf4[((((size_t)bh * 32 + chv) * 8 + ct) * 4 + sp) * 32 + ln] = r;
        }
    }
}

// ---------------- Proj GEMM (bf16 m16n8k16 mma) + bias + residual ----------------
__global__ void __launch_bounds__(256) gemm_proj(const float* __restrict__ W,
                                                 const float* __restrict__ bias,
                                                 const float* __restrict__ resid,
                                                 float* __restrict__ outp) {
    __shared__ uint4 Af[8 * 32];
    __shared__ uint2 Bf[16 * 32];
    const int tid = threadIdx.x, wid = tid >> 5, lane = tid & 31;
    const int gr = lane >> 2, tg = lane & 3;
    const int n0 = blockIdx.x * 128, mb = blockIdx.y, b = blockIdx.z;
    const int wm = wid & 3, wn = wid >> 2;

    float acc[2][8][4] = {};
    const float* Abase = W + (size_t)(mb * 128) * 256;

    for (int k0 = 0; k0 < 256; k0 += 16) {
        {
            const float* ap = Abase + (size_t)(wid * 16 + gr) * 256 + k0 + 2 * tg;
            float2 w00 = *(const float2*)ap;
            float2 w10 = *(const float2*)(ap + 8 * 256);
            float2 w01 = *(const float2*)(ap + 8);
            float2 w11 = *(const float2*)(ap + 8 * 256 + 8);
            uint4 u;
            u.x = pbf2(w00.x, w00.y);
            u.y = pbf2(w10.x, w10.y);
            u.z = pbf2(w01.x, w01.y);
            u.w = pbf2(w11.x, w11.y);
            Af[wid * 32 + lane] = u;
        }
#pragma unroll
        for (int i = 0; i < 2; i++) {
            int u_ = wid * 2 + i;
            int n = n0 + u_ * 8 + gr;
            int c0 = k0 + 2 * tg;
            const float* xp = g_ao + ((size_t)(b * 256 + c0)) * 4096 + n;
            uint2 v;
            v.x = pbf2(xp[0], xp[4096]);
            v.y = pbf2(xp[8 * 4096], xp[9 * 4096]);
            Bf[u_ * 32 + lane] = v;
        }
        __syncthreads();
        uint4 a0 = Af[(wm * 2 + 0) * 32 + lane];
        uint4 a1 = Af[(wm * 2 + 1) * 32 + lane];
#pragma unroll
        for (int u_ = 0; u_ < 8; u_++) {
            uint2 bb = Bf[(wn * 8 + u_) * 32 + lane];
            mma_bf16(acc[0][u_], a0.x, a0.y, a0.z, a0.w, bb.x, bb.y);
            mma_bf16(acc[1][u_], a1.x, a1.y, a1.z, a1.w, bb.x, bb.y);
        }
        __syncthreads();
    }

#pragma unroll
    for (int t = 0; t < 2; t++) {
        int o = mb * 128 + wm * 32 + t * 16 + gr;
        float bi0 = bias[o], bi1 = bias[o + 8];
#pragma unroll
        for (int u_ = 0; u_ < 8; u_++) {
            size_t off = ((size_t)(b * 256 + o)) * 4096 + n0 + wn * 64 + u_ * 8 + 2 * tg;
            float2 r0 = *(const float2*)(resid + off);
            float2 o0;
            o0.x = acc[t][u_][0] + bi0 + r0.x;
            o0.y = acc[t][u_][1] + bi0 + r0.y;
            *(float2*)(outp + off) = o0;
            size_t off8 = off + 8 * 4096;
            float2 r1 = *(const float2*)(resid + off8);
            float2 o1;
            o1.x = acc[t][u_][2] + bi1 + r1.x;
            o1.y = acc[t][u_][3] + bi1 + r1.y;
            *(float2*)(outp + off8) = o1;
        }
    }
}

// ---------------- bf16 mma flash attention (R8 version, verbatim) ----------------
// grid (32 q-tiles, 16 bh), 128 thr = 4 warps x 32 q rows (2 m16 A-tiles each).
// smem: 3 stages x (K 16KB | V 16KB) = 96KB.
#define ATT_SMEM 98304

__global__ void __launch_bounds__(128, 2) attn_mma() {
    extern __shared__ char smc[];
    uint32_t sbase;
    asm("{ .reg .u64 t; cvta.to.shared.u64 t, %1; cvt.u32.u64 %0, t; }" : "=r"(sbase) : "l"(smc));

    const int tid = threadIdx.x, wid = tid >> 5, lane = tid & 31;
    const int gr = lane >> 2, tg = lane & 3;
    const int qt = blockIdx.x, bh = blockIdx.y;
    const int b = bh >> 2, hh = bh & 3;
    const int w32 = wid * 32;

    const __nv_bfloat16* qg = g_qb + ((size_t)bh * 4096 + qt * 128) * 64;
    const uint4* kfg = g_kf4 + (size_t)bh * 32768;
    const uint4* vfg = g_vf4 + (size_t)bh * 32768;

    uint32_t qa[2][4][4];
#pragma unroll
    for (int at = 0; at < 2; at++) {
#pragma unroll
        for (int s = 0; s < 4; s++) {
            const __nv_bfloat16* base = qg + (size_t)(w32 + at * 16 + gr) * 64 + s * 16 + 2 * tg;
            qa[at][s][0] = *(const uint32_t*)(base);
            qa[at][s][1] = *(const uint32_t*)(base + 8 * 64);
            qa[at][s][2] = *(const uint32_t*)(base + 8);
            qa[at][s][3] = *(const uint32_t*)(base + 8 * 64 + 8);
        }
    }

    float oacc[2][8][4] = {};
    float rs[2][2] = {};

#define PREFETCH(ch) do {                                                     \
        int _c = (ch);                                                       \
        if (_c < 32) {                                                       \
            uint32_t _sk = sbase + (uint32_t)(_c % 3) * 32768;               \
            const uint4* _gk = kfg + (size_t)_c * 1024;                      \
            const uint4* _gv = vfg + (size_t)_c * 1024;                      \
            _Pragma("unroll")                                                \
            for (int _i = 0; _i < 8; _i++)                                   \
                cp16(_sk + (tid + _i * 128) * 16, _gk + tid + _i * 128);     \
            _Pragma("unroll")                                                \
            for (int _i = 0; _i < 8; _i++)                                   \
                cp16(_sk + 16384 + (tid + _i * 128) * 16, _gv + tid + _i * 128); \
        }                                                                    \
        CP_COMMIT();                                                         \
    } while (0)

#define S_CALC(dst, g) do {                                                  \
        _Pragma("unroll")                                                    \
        for (int _u = 0; _u < 4; _u++) {                                     \
            uint4 _k0 = Kf4[(((g) * 4 + _u) * 2 + 0) * 32 + lane];           \
            uint4 _k1 = Kf4[(((g) * 4 + _u) * 2 + 1) * 32 + lane];           \
            _Pragma("unroll")                                                \
            for (int _at = 0; _at < 2; _at++) {                              \
                dst[_at][_u][0] = 0.f; dst[_at][_u][1] = 0.f;                \
                dst[_at][_u][2] = 0.f; dst[_at][_u][3] = 0.f;                \
                mma_bf16(dst[_at][_u], qa[_at][0][0], qa[_at][0][1], qa[_at][0][2], qa[_at][0][3], _k0.x, _k0.y); \
                mma_bf16(dst[_at][_u], qa[_at][1][0], qa[_at][1][1], qa[_at][1][2], qa[_at][1][3], _k0.z, _k0.w); \
                mma_bf16(dst[_at][_u], qa[_at][2][0], qa[_at][2][1], qa[_at][2][2], qa[_at][2][3], _k1.x, _k1.y); \
                mma_bf16(dst[_at][_u], qa[_at][3][0], qa[_at][3][1], qa[_at][3][2], qa[_at][3][3], _k1.z, _k1.w); \
            }                                                                \
        }                                                                    \
    } while (0)

#define E_CALC(pdst, src) do {                                               \
        _Pragma("unroll")                                                    \
        for (int _at = 0; _at < 2; _at++) {                                  \
            _Pragma("unroll")                                                \
            for (int _u = 0; _u < 4; _u++) {                                 \
                float _e0 = ex2(src[_at][_u][0]);                            \
                float _e1 = ex2(src[_at][_u][1]);                            \
                float _e2 = ex2(src[_at][_u][2]);                            \
                float _e3 = ex2(src[_at][_u][3]);                            \
                rs[_at][0] += _e0 + _e1;                                     \
                rs[_at][1] += _e2 + _e3;                                     \
                pdst[_at][_u][0] = pbf2(_e0, _e1);                           \
                pdst[_at][_u][1] = pbf2(_e2, _e3);                           \
            }                                                                \
        }                                                                    \
    } while (0)

#define V_CALC(g, psrc) do {                                                 \
        _Pragma("unroll")                                                    \
        for (int _ct = 0; _ct < 8; _ct++) {                                  \
            uint4 _v = Vf4[(_ct * 4 + (g)) * 32 + lane];                     \
            _Pragma("unroll")                                                \
            for (int _at = 0; _at < 2; _at++) {                              \
                mma_bf16(oacc[_at][_ct], psrc[_at][0][0], psrc[_at][0][1],   \
                         psrc[_at][1][0], psrc[_at][1][1], _v.x, _v.y);      \
                mma_bf16(oacc[_at][_ct], psrc[_at][2][0], psrc[_at][2][1],   \
                         psrc[_at][3][0], psrc[_at][3][1], _v.z, _v.w);      \
            }                                                                \
        }                                                                    \
    } while (0)

    PREFETCH(0);
    PREFETCH(1);

    for (int ch = 0; ch < 32; ch++) {
        CP_WAIT1();
        __syncthreads();
        PREFETCH(ch + 2);

        const uint4* Kf4 = (const uint4*)(smc + (ch % 3) * 32768);
        const uint4* Vf4 = (const uint4*)(smc + (ch % 3) * 32768 + 16384);

        float sA[2][4][4], sB[2][4][4];
        uint32_t pA[2][4][2], pB[2][4][2];

        S_CALC(sA, 0);
        E_CALC(pA, sA);
        S_CALC(sB, 1);
        V_CALC(0, pA);
        E_CALC(pB, sB);
        S_CALC(sA, 2);
        V_CALC(1, pB);
        E_CALC(pA, sA);
        S_CALC(sB, 3);
        V_CALC(2, pA);
        E_CALC(pB, sB);
        V_CALC(3, pB);
    }
#undef PREFETCH
#undef S_CALC
#undef E_CALC
#undef V_CALC

    float ri[2][2];
#pragma unroll
    for (int at = 0; at < 2; at++) {
#pragma unroll
        for (int r = 0; r < 2; r++) {
            float v = rs[at][r];
            v += __shfl_xor_sync(0xffffffffu, v, 1);
            v += __shfl_xor_sync(0xffffffffu, v, 2);
            ri[at][r] = 1.0f / v;
        }
    }

    float* Os = (float*)smc;
    __syncthreads();
#pragma unroll
    for (int at = 0; at < 2; at++) {
#pragma unroll
        for (int ct = 0; ct < 8; ct++) {
            int c = ct * 8 + 2 * tg;
            int q0 = w32 + at * 16 + gr;
            Os[(size_t)c * 132 + q0] = oacc[at][ct][0] * ri[at][0];
            Os[(size_t)(c + 1) * 132 + q0] = oacc[at][ct][1] * ri[at][0];
            Os[(size_t)c * 132 + q0 + 8] = oacc[at][ct][2] * ri[at][1];
            Os[(size_t)(c + 1) * 132 + q0 + 8] = oacc[at][ct][3] * ri[at][1];
        }
    }
    __syncthreads();

    float* dst = g_ao + ((size_t)(b * 256 + hh * 64)) * 4096 + qt * 128;
#pragma unroll
    for (int p = 0; p < 16; p++) {
        int idx = tid + p * 128;
        int c = idx >> 5, q4 = idx & 31;
        float4 v = *(const float4*)(Os + (size_t)c * 132 + q4 * 4);
        *(float4*)(dst + (size_t)c * 4096 + q4 * 4) = v;
    }
}

// ---------------- launch ----------------
extern "C" void kernel_launch(void* const* d_in, const int* in_sizes, int n_in,
                              void* d_out, int out_size) {
    (void)in_sizes; (void)n_in; (void)out_size;
    const float* x      = (const float*)d_in[0];
    const float* norm_w = (const float*)d_in[1];
    const float* norm_b = (const float*)d_in[2];
    const float* qkv_w  = (const float*)d_in[3];
    const float* qkv_b  = (const float*)d_in[4];
    const float* proj_w = (const float*)d_in[5];
    const float* proj_b = (const float*)d_in[6];
    float* out = (float*)d_out;

    cudaFuncSetAttribute(attn_mma, cudaFuncAttributeMaxDynamicSharedMemorySize, ATT_SMEM);

    gn_partial<<<dim3(32, 16), 256>>>(x);
    gn_finalize<<<1, 32>>>();

    gemm_qkv<<<dim3(32, 6, 4), 256, QKV_SMEM>>>(qkv_w, x, qkv_b, norm_w, norm_b);

    attn_mma<<<dim3(32, 16), 128, ATT_SMEM>>>();

    gemm_proj<<<dim3(32, 2, 4), 256>>>(proj_w, proj_b, x, out);
}

// round 11
// speedup vs baseline: 1.2068x; 1.0220x over previous
#include <cuda_runtime.h>
#include <cuda_bf16.h>
#include <cuda_fp16.h>
#include <math.h>
#include <cstdint>

#define EPSV 1e-5f

// ---------------- scratch (device globals; allocation-free) ----------------
__device__ __nv_bfloat16 g_qb[16 * 4096 * 64];   // q: [bh][n][c], pre-scaled 0.125*log2e
__device__ uint4 g_kf4[16 * 512 * 2 * 32];       // K frags (bf16): [bh][kt][sp][lane]
__device__ uint4 g_vf4[16 * 32 * 8 * 4 * 32];    // V frags (fp16): [bh][chunk][ct][sp][lane]
__device__ float g_ao[4 * 256 * 4096];           // attention out [b][c][n] fp32
__device__ float g_part[32 * 16 * 2];
__device__ float g_mean[32];
__device__ float g_rstd[32];

// ======================= helpers =======================
__device__ __forceinline__ uint32_t pbf2(float lo, float hi) {
    __nv_bfloat162 t = __floats2bfloat162_rn(lo, hi);
    return *(uint32_t*)&t;
}
__device__ __forceinline__ uint32_t ph2(float lo, float hi) {
    __half2 t = __floats2half2_rn(lo, hi);
    return *(uint32_t*)&t;
}
__device__ __forceinline__ uint32_t ex2h2(uint32_t h2) {
    uint32_t r;
    asm("ex2.approx.f16x2 %0, %1;" : "=r"(r) : "r"(h2));
    return r;
}
__device__ __forceinline__ void mma_bf16(float d[4], const uint32_t a0, const uint32_t a1,
                                         const uint32_t a2, const uint32_t a3,
                                         const uint32_t b0, const uint32_t b1) {
    asm volatile("mma.sync.aligned.m16n8k16.row.col.f32.bf16.bf16.f32 "
                 "{%0,%1,%2,%3}, {%4,%5,%6,%7}, {%8,%9}, {%0,%1,%2,%3};"
                 : "+f"(d[0]), "+f"(d[1]), "+f"(d[2]), "+f"(d[3])
                 : "r"(a0), "r"(a1), "r"(a2), "r"(a3), "r"(b0), "r"(b1));
}
__device__ __forceinline__ void mma_f16(float d[4], const uint32_t a0, const uint32_t a1,
                                        const uint32_t a2, const uint32_t a3,
                                        const uint32_t b0, const uint32_t b1) {
    asm volatile("mma.sync.aligned.m16n8k16.row.col.f32.f16.f16.f32 "
                 "{%0,%1,%2,%3}, {%4,%5,%6,%7}, {%8,%9}, {%0,%1,%2,%3};"
                 : "+f"(d[0]), "+f"(d[1]), "+f"(d[2]), "+f"(d[3])
                 : "r"(a0), "r"(a1), "r"(a2), "r"(a3), "r"(b0), "r"(b1));
}
__device__ __forceinline__ void cp16(uint32_t saddr, const void* gaddr) {
    asm volatile("cp.async.cg.shared.global [%0], [%1], 16;" :: "r"(saddr), "l"(gaddr));
}
#define CP_COMMIT() asm volatile("cp.async.commit_group;" ::: "memory")
#define CP_WAIT1()  asm volatile("cp.async.wait_group 1;" ::: "memory")

// ---------------- GroupNorm stats ----------------
__global__ void gn_partial(const float* __restrict__ x) {
    int bg = blockIdx.x;
    int chunk = blockIdx.y;
    const float4* p = (const float4*)(x + (size_t)bg * 32 * 4096 + (size_t)chunk * 8192);
    float s = 0.f, q = 0.f;
#pragma unroll
    for (int i = 0; i < 8; i++) {
        float4 v = p[threadIdx.x + i * 256];
        s += v.x + v.y + v.z + v.w;
        q += v.x * v.x + v.y * v.y + v.z * v.z + v.w * v.w;
    }
    __shared__ float ss[256], sq[256];
    ss[threadIdx.x] = s; sq[threadIdx.x] = q;
    __syncthreads();
    for (int o = 128; o > 0; o >>= 1) {
        if (threadIdx.x < o) {
            ss[threadIdx.x] += ss[threadIdx.x + o];
            sq[threadIdx.x] += sq[threadIdx.x + o];
        }
        __syncthreads();
    }
    if (threadIdx.x == 0) {
        g_part[(bg * 16 + chunk) * 2 + 0] = ss[0];
        g_part[(bg * 16 + chunk) * 2 + 1] = sq[0];
    }
}

__global__ void gn_finalize() {
    int t = threadIdx.x;
    float s = 0.f, q = 0.f;
#pragma unroll
    for (int i = 0; i < 16; i++) {
        s += g_part[(t * 16 + i) * 2 + 0];
        q += g_part[(t * 16 + i) * 2 + 1];
    }
    const float inv = 1.0f / 131072.0f;
    float mean = s * inv;
    float var = q * inv - mean * mean;
    g_mean[t] = mean;
    g_rstd[t] = rsqrtf(var + EPSV);
}

// ---------------- QKV GEMM (bf16 m16n8k16 mma, GN fused into B staging) -----------
// grid (32 nb, 6 mb, 4 b), 256 thr. mb: 0,1=q 2,3=k 4,5=v. C tile 128x128.
// q/k staged bf16; v staged fp16 (consumed by fp16 PV mma).
#define QKV_SMEM 35328

__global__ void __launch_bounds__(256) gemm_qkv(const float* __restrict__ W,
                                                const float* __restrict__ x,
                                                const float* __restrict__ bias,
                                                const float* __restrict__ nw,
                                                const float* __restrict__ nbv) {
    extern __shared__ char sm[];
    uint4* Af = (uint4*)sm;                         // 8 frags * 32 lanes
    uint2* Bf = (uint2*)(sm + 4096);                // 16 frags * 32 lanes
    unsigned short* Ost = (unsigned short*)sm;      // [128][130] 16-bit overlay
    float* sc = (float*)(sm + 33280);
    float* sh = (float*)(sm + 34304);

    const int tid = threadIdx.x, wid = tid >> 5, lane = tid & 31;
    const int gr = lane >> 2, tg = lane & 3;
    const int n0 = blockIdx.x * 128, mb = blockIdx.y, b = blockIdx.z;
    const int wm = wid & 3, wn = wid >> 2;

    {
        int c = tid;
        int bg = b * 8 + (c >> 5);
        float s = g_rstd[bg] * nw[c];
        sc[c] = s;
        sh[c] = nbv[c] - g_mean[bg] * s;
    }
    __syncthreads();

    float acc[2][8][4] = {};
    const float* Abase = W + (size_t)(mb * 128) * 256;

    for (int k0 = 0; k0 < 256; k0 += 16) {
        {
            const float* ap = Abase + (size_t)(wid * 16 + gr) * 256 + k0 + 2 * tg;
            float2 w00 = *(const float2*)ap;
            float2 w10 = *(const float2*)(ap + 8 * 256);
            float2 w01 = *(const float2*)(ap + 8);
            float2 w11 = *(const float2*)(ap + 8 * 256 + 8);
            uint4 u;
            u.x = pbf2(w00.x, w00.y);
            u.y = pbf2(w10.x, w10.y);
            u.z = pbf2(w01.x, w01.y);
            u.w = pbf2(w11.x, w11.y);
            Af[wid * 32 + lane] = u;
        }
#pragma unroll
        for (int i = 0; i < 2; i++) {
            int u_ = wid * 2 + i;
            int n = n0 + u_ * 8 + gr;
            int c0 = k0 + 2 * tg;
            const float* xp = x + ((size_t)(b * 256 + c0)) * 4096 + n;
            float h00 = xp[0] * sc[c0] + sh[c0];
            float h01 = xp[4096] * sc[c0 + 1] + sh[c0 + 1];
            float h10 = xp[8 * 4096] * sc[c0 + 8] + sh[c0 + 8];
            float h11 = xp[9 * 4096] * sc[c0 + 9] + sh[c0 + 9];
            uint2 v;
            v.x = pbf2(h00, h01);
            v.y = pbf2(h10, h11);
            Bf[u_ * 32 + lane] = v;
        }
        __syncthreads();
        uint4 a0 = Af[(wm * 2 + 0) * 32 + lane];
        uint4 a1 = Af[(wm * 2 + 1) * 32 + lane];
#pragma unroll
        for (int u_ = 0; u_ < 8; u_++) {
            uint2 bb = Bf[(wn * 8 + u_) * 32 + lane];
            mma_bf16(acc[0][u_], a0.x, a0.y, a0.z, a0.w, bb.x, bb.y);
            mma_bf16(acc[1][u_], a1.x, a1.y, a1.z, a1.w, bb.x, bb.y);
        }
        __syncthreads();
    }

    // stage 16-bit [o_local][n_local] (q pre-scaled by 0.125*log2e; v as fp16)
    const float scale = (mb < 2) ? 0.125f * 1.4426950408889634f : 1.0f;
    const bool v_half = (mb >= 4);
#pragma unroll
    for (int t = 0; t < 2; t++) {
        int o_l = wm * 32 + t * 16 + gr;
        float bi0 = bias[mb * 128 + o_l];
        float bi1 = bias[mb * 128 + o_l + 8];
#pragma unroll
        for (int u_ = 0; u_ < 8; u_++) {
            int n_l = wn * 64 + u_ * 8 + 2 * tg;
            float v00 = (acc[t][u_][0] + bi0) * scale, v01 = (acc[t][u_][1] + bi0) * scale;
            float v10 = (acc[t][u_][2] + bi1) * scale, v11 = (acc[t][u_][3] + bi1) * scale;
            uint32_t w0 = v_half ? ph2(v00, v01) : pbf2(v00, v01);
            uint32_t w1 = v_half ? ph2(v10, v11) : pbf2(v10, v11);
            *(uint32_t*)&Ost[o_l * 130 + n_l] = w0;
            *(uint32_t*)&Ost[(o_l + 8) * 130 + n_l] = w1;
        }
    }
    __syncthreads();

    if (mb < 2) {
#pragma unroll
        for (int p = 0; p < 32; p++) {
            int idx = tid + p * 256;
            int n = idx >> 6;
            int ho = (idx >> 5) & 1;
            int cw = idx & 31;
            unsigned short lo = Ost[(ho * 64 + 2 * cw) * 130 + n];
            unsigned short hi = Ost[(ho * 64 + 2 * cw + 1) * 130 + n];
            uint32_t val = (uint32_t)lo | ((uint32_t)hi << 16);
            int bh = b * 4 + mb * 2 + ho;
            ((uint32_t*)g_qb)[((size_t)bh * 4096 + n0 + n) * 32 + cw] = val;
        }
    } else if (mb < 4) {
#pragma unroll
        for (int p = 0; p < 8; p++) {
            int e = tid + p * 256;
            int ln = e & 31, sp = (e >> 5) & 1, kt = (e >> 6) & 15, ho = e >> 10;
            int egr = ln >> 2, etg = ln & 3;
            int n = kt * 8 + egr;
            uint4 r;
            {
                int c0 = ho * 64 + (2 * sp) * 16 + 2 * etg;
                r.x = (uint32_t)Ost[c0 * 130 + n] | ((uint32_t)Ost[(c0 + 1) * 130 + n] << 16);
                r.y = (uint32_t)Ost[(c0 + 8) * 130 + n] | ((uint32_t)Ost[(c0 + 9) * 130 + n] << 16);
            }
            {
                int c0 = ho * 64 + (2 * sp + 1) * 16 + 2 * etg;
                r.z = (uint32_t)Ost[c0 * 130 + n] | ((uint32_t)Ost[(c0 + 1) * 130 + n] << 16);
                r.w = (uint32_t)Ost[(c0 + 8) * 130 + n] | ((uint32_t)Ost[(c0 + 9) * 130 + n] << 16);
            }
            int bh = b * 4 + (mb & 1) * 2 + ho;
            g_kf4[(((size_t)bh * 512 + (n0 >> 3) + kt) * 2 + sp) * 32 + ln] = r;
        }
    } else {
        int chv = blockIdx.x;
#pragma unroll
        for (int p = 0; p < 8; p++) {
            int e = tid + p * 256;
            int ln = e & 31, sp = (e >> 5) & 3, ct = (e >> 7) & 7, ho = e >> 10;
            int egr = ln >> 2, etg = ln & 3;
            int c = ho * 64 + ct * 8 + egr;
            uint4 r;
            {
                int nn = (2 * sp) * 16 + 2 * etg;
                r.x = *(uint32_t*)&Ost[c * 130 + nn];
                r.y = *(uint32_t*)&Ost[c * 130 + nn + 8];
            }
            {
                int nn = (2 * sp + 1) * 16 + 2 * etg;
                r.z = *(uint32_t*)&Ost[c * 130 + nn];
                r.w = *(uint32_t*)&Ost[c * 130 + nn + 8];
            }
            int bh = b * 4 + (mb - 4) * 2 + ho;
            g_vf4[((((size_t)bh * 32 + chv) * 8 + ct) * 4 + sp) * 32 + ln] = r;
        }
    }
}

// ---------------- Proj GEMM (bf16 m16n8k16 mma) + bias + residual ----------------
__global__ void __launch_bounds__(256) gemm_proj(const float* __restrict__ W,
                                                 const float* __restrict__ bias,
                                                 const float* __restrict__ resid,
                                                 float* __restrict__ outp) {
    __shared__ uint4 Af[8 * 32];
    __shared__ uint2 Bf[16 * 32];
    const int tid = threadIdx.x, wid = tid >> 5, lane = tid & 31;
    const int gr = lane >> 2, tg = lane & 3;
    const int n0 = blockIdx.x * 128, mb = blockIdx.y, b = blockIdx.z;
    const int wm = wid & 3, wn = wid >> 2;

    float acc[2][8][4] = {};
    const float* Abase = W + (size_t)(mb * 128) * 256;

    for (int k0 = 0; k0 < 256; k0 += 16) {
        {
            const float* ap = Abase + (size_t)(wid * 16 + gr) * 256 + k0 + 2 * tg;
            float2 w00 = *(const float2*)ap;
            float2 w10 = *(const float2*)(ap + 8 * 256);
            float2 w01 = *(const float2*)(ap + 8);
            float2 w11 = *(const float2*)(ap + 8 * 256 + 8);
            uint4 u;
            u.x = pbf2(w00.x, w00.y);
            u.y = pbf2(w10.x, w10.y);
            u.z = pbf2(w01.x, w01.y);
            u.w = pbf2(w11.x, w11.y);
            Af[wid * 32 + lane] = u;
        }
#pragma unroll
        for (int i = 0; i < 2; i++) {
            int u_ = wid * 2 + i;
            int n = n0 + u_ * 8 + gr;
            int c0 = k0 + 2 * tg;
            const float* xp = g_ao + ((size_t)(b * 256 + c0)) * 4096 + n;
            uint2 v;
            v.x = pbf2(xp[0], xp[4096]);
            v.y = pbf2(xp[8 * 4096], xp[9 * 4096]);
            Bf[u_ * 32 + lane] = v;
        }
        __syncthreads();
        uint4 a0 = Af[(wm * 2 + 0) * 32 + lane];
        uint4 a1 = Af[(wm * 2 + 1) * 32 + lane];
#pragma unroll
        for (int u_ = 0; u_ < 8; u_++) {
            uint2 bb = Bf[(wn * 8 + u_) * 32 + lane];
            mma_bf16(acc[0][u_], a0.x, a0.y, a0.z, a0.w, bb.x, bb.y);
            mma_bf16(acc[1][u_], a1.x, a1.y, a1.z, a1.w, bb.x, bb.y);
        }
        __syncthreads();
    }

#pragma unroll
    for (int t = 0; t < 2; t++) {
        int o = mb * 128 + wm * 32 + t * 16 + gr;
        float bi0 = bias[o], bi1 = bias[o + 8];
#pragma unroll
        for (int u_ = 0; u_ < 8; u_++) {
            size_t off = ((size_t)(b * 256 + o)) * 4096 + n0 + wn * 64 + u_ * 8 + 2 * tg;
            float2 r0 = *(const float2*)(resid + off);
            float2 o0;
            o0.x = acc[t][u_][0] + bi0 + r0.x;
            o0.y = acc[t][u_][1] + bi0 + r0.y;
            *(float2*)(outp + off) = o0;
            size_t off8 = off + 8 * 4096;
            float2 r1 = *(const float2*)(resid + off8);
            float2 o1;
            o1.x = acc[t][u_][2] + bi1 + r1.x;
            o1.y = acc[t][u_][3] + bi1 + r1.y;
            *(float2*)(outp + off8) = o1;
        }
    }
}

// ---------------- flash attention: bf16 QK, f16x2 ex2 softmax, fp16 PV -----------
// grid (32 q-tiles, 16 bh), 128 thr = 4 warps x 32 q rows (2 m16 A-tiles each).
// smem: 3 stages x (K 16KB | V 16KB) = 96KB.
// Rowsum via extra ones-column fp16 MMA (fp32 acc, every lane gets full sum).
#define ATT_SMEM 98304
#define ONE2 0x3C003C00u

__global__ void __launch_bounds__(128, 2) attn_mma() {
    extern __shared__ char smc[];
    uint32_t sbase;
    asm("{ .reg .u64 t; cvta.to.shared.u64 t, %1; cvt.u32.u64 %0, t; }" : "=r"(sbase) : "l"(smc));

    const int tid = threadIdx.x, wid = tid >> 5, lane = tid & 31;
    const int gr = lane >> 2, tg = lane & 3;
    const int qt = blockIdx.x, bh = blockIdx.y;
    const int b = bh >> 2, hh = bh & 3;
    const int w32 = wid * 32;

    const __nv_bfloat16* qg = g_qb + ((size_t)bh * 4096 + qt * 128) * 64;
    const uint4* kfg = g_kf4 + (size_t)bh * 32768;
    const uint4* vfg = g_vf4 + (size_t)bh * 32768;

    uint32_t qa[2][4][4];
#pragma unroll
    for (int at = 0; at < 2; at++) {
#pragma unroll
        for (int s = 0; s < 4; s++) {
            const __nv_bfloat16* base = qg + (size_t)(w32 + at * 16 + gr) * 64 + s * 16 + 2 * tg;
            qa[at][s][0] = *(const uint32_t*)(base);
            qa[at][s][1] = *(const uint32_t*)(base + 8 * 64);
            qa[at][s][2] = *(const uint32_t*)(base + 8);
            qa[at][s][3] = *(const uint32_t*)(base + 8 * 64 + 8);
        }
    }

    float oacc[2][8][4] = {};
    float rsacc[2][4] = {};

#define PREFETCH(ch) do {                                                     \
        int _c = (ch);                                                       \
        if (_c < 32) {                                                       \
            uint32_t _sk = sbase + (uint32_t)(_c % 3) * 32768;               \
            const uint4* _gk = kfg + (size_t)_c * 1024;                      \
            const uint4* _gv = vfg + (size_t)_c * 1024;                      \
            _Pragma("unroll")                                                \
            for (int _i = 0; _i < 8; _i++)                                   \
                cp16(_sk + (tid + _i * 128) * 16, _gk + tid + _i * 128);     \
            _Pragma("unroll")                                                \
            for (int _i = 0; _i < 8; _i++)                                   \
                cp16(_sk + 16384 + (tid + _i * 128) * 16, _gv + tid + _i * 128); \
        }                                                                    \
        CP_COMMIT();                                                         \
    } while (0)

#define S_CALC(dst, g) do {                                                  \
        _Pragma("unroll")                                                    \
        for (int _u = 0; _u < 4; _u++) {                                     \
            uint4 _k0 = Kf4[(((g) * 4 + _u) * 2 + 0) * 32 + lane];           \
            uint4 _k1 = Kf4[(((g) * 4 + _u) * 2 + 1) * 32 + lane];           \
            _Pragma("unroll")                                                \
            for (int _at = 0; _at < 2; _at++) {                              \
                dst[_at][_u][0] = 0.f; dst[_at][_u][1] = 0.f;                \
                dst[_at][_u][2] = 0.f; dst[_at][_u][3] = 0.f;                \
                mma_bf16(dst[_at][_u], qa[_at][0][0], qa[_at][0][1], qa[_at][0][2], qa[_at][0][3], _k0.x, _k0.y); \
                mma_bf16(dst[_at][_u], qa[_at][1][0], qa[_at][1][1], qa[_at][1][2], qa[_at][1][3], _k0.z, _k0.w); \
                mma_bf16(dst[_at][_u], qa[_at][2][0], qa[_at][2][1], qa[_at][2][2], qa[_at][2][3], _k1.x, _k1.y); \
                mma_bf16(dst[_at][_u], qa[_at][3][0], qa[_at][3][1], qa[_at][3][2], qa[_at][3][3], _k1.z, _k1.w); \
            }                                                                \
        }                                                                    \
    } while (0)

    // P = 2^S via f16x2 ex2 (half the MUFU ops; P stays fp16 = PV A-frag)
#define E_CALC(pdst, src) do {                                               \
        _Pragma("unroll")                                                    \
        for (int _at = 0; _at < 2; _at++) {                                  \
            _Pragma("unroll")                                                \
            for (int _u = 0; _u < 4; _u++) {                                 \
                pdst[_at][_u][0] = ex2h2(ph2(src[_at][_u][0], src[_at][_u][1])); \
                pdst[_at][_u][1] = ex2h2(ph2(src[_at][_u][2], src[_at][_u][3])); \
            }                                                                \
        }                                                                    \
    } while (0)

    // O += P V^T (fp16 mma) + rowsum via ones-column MMA (fp32 acc, exact)
#define V_CALC(g, psrc) do {                                                 \
        _Pragma("unroll")                                                    \
        for (int _ct = 0; _ct < 8; _ct++) {                                  \
            uint4 _v = Vf4[(_ct * 4 + (g)) * 32 + lane];                     \
            _Pragma("unroll")                                                \
            for (int _at = 0; _at < 2; _at++) {                              \
                mma_f16(oacc[_at][_ct], psrc[_at][0][0], psrc[_at][0][1],    \
                        psrc[_at][1][0], psrc[_at][1][1], _v.x, _v.y);       \
                mma_f16(oacc[_at][_ct], psrc[_at][2][0], psrc[_at][2][1],    \
                        psrc[_at][3][0], psrc[_at][3][1], _v.z, _v.w);       \
            }                                                                \
        }                                                                    \
        _Pragma("unroll")                                                    \
        for (int _at = 0; _at < 2; _at++) {                                  \
            mma_f16(rsacc[_at], psrc[_at][0][0], psrc[_at][0][1],            \
                    psrc[_at][1][0], psrc[_at][1][1], ONE2, ONE2);           \
            mma_f16(rsacc[_at], psrc[_at][2][0], psrc[_at][2][1],            \
                    psrc[_at][3][0], psrc[_at][3][1], ONE2, ONE2);           \
        }                                                                    \
    } while (0)

    PREFETCH(0);
    PREFETCH(1);

    for (int ch = 0; ch < 32; ch++) {
        CP_WAIT1();
        __syncthreads();
        PREFETCH(ch + 2);

        const uint4* Kf4 = (const uint4*)(smc + (ch % 3) * 32768);
        const uint4* Vf4 = (const uint4*)(smc + (ch % 3) * 32768 + 16384);

        float sA[2][4][4], sB[2][4][4];
        uint32_t pA[2][4][2], pB[2][4][2];

        S_CALC(sA, 0);
        E_CALC(pA, sA);
        S_CALC(sB, 1);
        V_CALC(0, pA);
        E_CALC(pB, sB);
        S_CALC(sA, 2);
        V_CALC(1, pB);
        E_CALC(pA, sA);
        S_CALC(sB, 3);
        V_CALC(2, pA);
        E_CALC(pB, sB);
        V_CALC(3, pB);
    }
#undef PREFETCH
#undef S_CALC
#undef E_CALC
#undef V_CALC

    // rowsums: every lane of rsacc holds the full row sum (ones columns)
    float ri[2][2];
#pragma unroll
    for (int at = 0; at < 2; at++) {
        ri[at][0] = 1.0f / rsacc[at][0];
        ri[at][1] = 1.0f / rsacc[at][2];
    }

    float* Os = (float*)smc;
    __syncthreads();
#pragma unroll
    for (int at = 0; at < 2; at++) {
#pragma unroll
        for (int ct = 0; ct < 8; ct++) {
            int c = ct * 8 + 2 * tg;
            int q0 = w32 + at * 16 + gr;
            Os[(size_t)c * 132 + q0] = oacc[at][ct][0] * ri[at][0];
            Os[(size_t)(c + 1) * 132 + q0] = oacc[at][ct][1] * ri[at][0];
            Os[(size_t)c * 132 + q0 + 8] = oacc[at][ct][2] * ri[at][1];
            Os[(size_t)(c + 1) * 132 + q0 + 8] = oacc[at][ct][3] * ri[at][1];
        }
    }
    __syncthreads();

    float* dst = g_ao + ((size_t)(b * 256 + hh * 64)) * 4096 + qt * 128;
#pragma unroll
    for (int p = 0; p < 16; p++) {
        int idx = tid + p * 128;
        int c = idx >> 5, q4 = idx & 31;
        float4 v = *(const float4*)(Os + (size_t)c * 132 + q4 * 4);
        *(float4*)(dst + (size_t)c * 4096 + q4 * 4) = v;
    }
}

// ---------------- launch ----------------
extern "C" void kernel_launch(void* const* d_in, const int* in_sizes, int n_in,
                              void* d_out, int out_size) {
    (void)in_sizes; (void)n_in; (void)out_size;
    const float* x      = (const float*)d_in[0];
    const float* norm_w = (const float*)d_in[1];
    const float* norm_b = (const float*)d_in[2];
    const float* qkv_w  = (const float*)d_in[3];
    const float* qkv_b  = (const float*)d_in[4];
    const float* proj_w = (const float*)d_in[5];
    const float* proj_b = (const float*)d_in[6];
    float* out = (float*)d_out;

    cudaFuncSetAttribute(attn_mma, cudaFuncAttributeMaxDynamicSharedMemorySize, ATT_SMEM);

    gn_partial<<<dim3(32, 16), 256>>>(x);
    gn_finalize<<<1, 32>>>();

    gemm_qkv<<<dim3(32, 6, 4), 256, QKV_SMEM>>>(qkv_w, x, qkv_b, norm_w, norm_b);

    attn_mma<<<dim3(32, 16), 128, ATT_SMEM>>>();

    gemm_proj<<<dim3(32, 2, 4), 256>>>(proj_w, proj_b, x, out);
}